// round 8
// baseline (speedup 1.0000x reference)
#include <cuda_runtime.h>

#define L_MAX   2048
#define BATCH   64
#define DDIM    256
#define CCH     512
#define NCHUNK  16
#define ROWS_PER_CHUNK (L_MAX / NCHUNK)   // 128
#define ROWS_PER_WARP  (ROWS_PER_CHUNK / 8) // 16

#define HQ_BLOCKS 2048
#define M_BLOCKS  96

// ---- scratch (no allocations allowed) ----
__device__ float g_hq[BATCH * DDIM];
__device__ float g_M[3 * DDIM];
__device__ float g_hardU[L_MAX * BATCH];
__device__ float g_part[BATCH * NCHUNK * DDIM];
__device__ float g_denp[BATCH * NCHUNK];

__device__ __forceinline__ float ftanh(float x) {
    float e = __expf(2.0f * x);
    return 1.0f - __fdividef(2.0f, e + 1.0f);
}

// ---------------------------------------------------------------------------
// Kernel 1: prep (warp-per-output, fully coalesced). Unchanged (7.2 us).
// ---------------------------------------------------------------------------
__global__ __launch_bounds__(256) void prep_kernel(
    const float* __restrict__ ht, const float* __restrict__ Wq,
    const float* __restrict__ Wap, const float* __restrict__ Wc,
    const float* __restrict__ bap)
{
    int warp = threadIdx.x >> 5, lane = threadIdx.x & 31;

    if (blockIdx.x < HQ_BLOCKS) {
        int gw = blockIdx.x * 8 + warp;
        int b = gw >> 8;
        int d = gw & 255;
        const float* htr = ht + b * DDIM;
        const float* wqr = Wq + (size_t)d * DDIM;
        float a = 0.f;
#pragma unroll
        for (int i = 0; i < DDIM / 32; i++) {
            int e = lane + 32 * i;
            a += htr[e] * wqr[e];
        }
#pragma unroll
        for (int off = 16; off; off >>= 1)
            a += __shfl_xor_sync(0xffffffffu, a, off);
        if (lane == 0) g_hq[b * DDIM + d] = a + bap[d];
    } else {
        int gw = (blockIdx.x - HQ_BLOCKS) * 8 + warp;
        int dd = gw / 3;
        int k  = gw % 3;
        const float* wr = Wap + (size_t)dd * CCH;
        float m = 0.f;
#pragma unroll
        for (int i = 0; i < CCH / 32; i++) {
            int c = lane + 32 * i;
            m += wr[c] * Wc[c * 3 + k];
        }
#pragma unroll
        for (int off = 16; off; off >>= 1)
            m += __shfl_xor_sync(0xffffffffu, m, off);
        if (lane == 0) g_M[k * DDIM + dd] = m;
    }
}

// ---------------------------------------------------------------------------
// Kernel 2: score — pure ctx_key stream. Warp per row, 2-row batches.
// Writes unnormalized hard mask to g_hardU. No val work at all.
// ---------------------------------------------------------------------------
__global__ __launch_bounds__(256) void score_kernel(
    const float* __restrict__ ctx_key, const float* __restrict__ ctx_mask,
    const float* __restrict__ past,
    const float* __restrict__ W_attn, const float* __restrict__ b_attn)
{
    __shared__ alignas(16) float s_past[ROWS_PER_CHUNK + 4]; // halo

    int b = blockIdx.y, chunk = blockIdx.x;
    int w = threadIdx.x >> 5, lane = threadIdx.x & 31;
    int d0 = lane * 4;        // [0,128)
    int d1 = 128 + lane * 4;  // [128,256)

    {
        int i = threadIdx.x;
        if (i < ROWS_PER_CHUNK + 2) {
            int g = chunk * ROWS_PER_CHUNK + i - 1;
            s_past[i] = (g >= 0 && g < L_MAX) ? past[b * L_MAX + g] : 0.f;
        }
    }
    __syncthreads();

    float4 hq0 = *reinterpret_cast<const float4*>(&g_hq[b * DDIM + d0]);
    float4 hq1 = *reinterpret_cast<const float4*>(&g_hq[b * DDIM + d1]);
    float4 M00 = *reinterpret_cast<const float4*>(&g_M[d0]);
    float4 M01 = *reinterpret_cast<const float4*>(&g_M[d1]);
    float4 M10 = *reinterpret_cast<const float4*>(&g_M[DDIM + d0]);
    float4 M11 = *reinterpret_cast<const float4*>(&g_M[DDIM + d1]);
    float4 M20 = *reinterpret_cast<const float4*>(&g_M[2 * DDIM + d0]);
    float4 M21 = *reinterpret_cast<const float4*>(&g_M[2 * DDIM + d1]);
    float4 Wa0 = *reinterpret_cast<const float4*>(&W_attn[d0]);
    float4 Wa1 = *reinterpret_cast<const float4*>(&W_attn[d1]);
    float ba = b_attn[0];

    int lbase = chunk * ROWS_PER_CHUNK + w * ROWS_PER_WARP;
#pragma unroll 2
    for (int rb = 0; rb < ROWS_PER_WARP / 2; rb++) {
        int l0 = lbase + rb * 2;
        float4 ka[2], kb[2];
#pragma unroll
        for (int j = 0; j < 2; j++) {
            size_t row = ((size_t)(l0 + j) * BATCH + b) * DDIM;
            ka[j] = *reinterpret_cast<const float4*>(ctx_key + row + d0);
            kb[j] = *reinterpret_cast<const float4*>(ctx_key + row + d1);
        }
        float sc[2];
#pragma unroll
        for (int j = 0; j < 2; j++) {
            int lr = w * ROWS_PER_WARP + rb * 2 + j;
            float pm = s_past[lr];
            float p0 = s_past[lr + 1];
            float pp = s_past[lr + 2];
            float s;
            s  = Wa0.x * ftanh(ka[j].x + hq0.x + pm * M00.x + p0 * M10.x + pp * M20.x);
            s += Wa0.y * ftanh(ka[j].y + hq0.y + pm * M00.y + p0 * M10.y + pp * M20.y);
            s += Wa0.z * ftanh(ka[j].z + hq0.z + pm * M00.z + p0 * M10.z + pp * M20.z);
            s += Wa0.w * ftanh(ka[j].w + hq0.w + pm * M00.w + p0 * M10.w + pp * M20.w);
            s += Wa1.x * ftanh(kb[j].x + hq1.x + pm * M01.x + p0 * M11.x + pp * M21.x);
            s += Wa1.y * ftanh(kb[j].y + hq1.y + pm * M01.y + p0 * M11.y + pp * M21.y);
            s += Wa1.z * ftanh(kb[j].z + hq1.z + pm * M01.z + p0 * M11.z + pp * M21.z);
            s += Wa1.w * ftanh(kb[j].w + hq1.w + pm * M01.w + p0 * M11.w + pp * M21.w);
            sc[j] = s;
        }
#pragma unroll
        for (int off = 16; off; off >>= 1) {
            sc[0] += __shfl_xor_sync(0xffffffffu, sc[0], off);
            sc[1] += __shfl_xor_sync(0xffffffffu, sc[1], off);
        }
        if (lane < 2) {
            int l = l0 + lane;
            float h = (sc[lane] + ba >= 0.f) ? ctx_mask[l * BATCH + b] : 0.f;
            g_hardU[l * BATCH + b] = h;
        }
    }
}

// ---------------------------------------------------------------------------
// Kernel 3: val — pure ctx_val stream, predicate known up front from smem.
// Thread d owns column d; walks 128 rows of its (b,chunk) tile.
// Also produces per-chunk denominator partials.
// ---------------------------------------------------------------------------
__global__ __launch_bounds__(256) void val_kernel(
    const float* __restrict__ ctx_val)
{
    __shared__ alignas(16) float s_h[ROWS_PER_CHUNK];

    int b = blockIdx.y, chunk = blockIdx.x;
    int lane = threadIdx.x & 31;

    if (threadIdx.x < ROWS_PER_CHUNK) {
        int l = chunk * ROWS_PER_CHUNK + threadIdx.x;
        s_h[threadIdx.x] = g_hardU[l * BATCH + b];
    }
    __syncthreads();

    int d = threadIdx.x;
    const float* vbase = ctx_val +
        ((size_t)chunk * ROWS_PER_CHUNK * BATCH + b) * DDIM + d;
    float acc = 0.f;
#pragma unroll 8
    for (int r = 0; r < ROWS_PER_CHUNK; r++) {
        float h = s_h[r];
        if (h != 0.f)
            acc += h * vbase[(size_t)r * (BATCH * DDIM)];
    }
    g_part[((size_t)b * NCHUNK + chunk) * DDIM + d] = acc;

    if (threadIdx.x < 32) {
        float c = 0.f;
#pragma unroll
        for (int r = 0; r < ROWS_PER_CHUNK / 32; r++)
            c += s_h[lane + 32 * r];
#pragma unroll
        for (int off = 16; off; off >>= 1)
            c += __shfl_xor_sync(0xffffffffu, c, off);
        if (lane == 0) g_denp[b * NCHUNK + chunk] = c;
    }
}

// ---------------------------------------------------------------------------
// Kernel 4: finish. Normalize; out = concat(ct.flat, hard.flat)
// ---------------------------------------------------------------------------
__global__ __launch_bounds__(256) void finish_kernel(float* __restrict__ out)
{
    int i = blockIdx.x * blockDim.x + threadIdx.x;
    if (i < BATCH * DDIM) {
        int b = i >> 8;
        int d = i & (DDIM - 1);
        float den = 0.f;
#pragma unroll
        for (int c = 0; c < NCHUNK; c++) den += g_denp[b * NCHUNK + c];
        float ct = 0.f;
#pragma unroll
        for (int c = 0; c < NCHUNK; c++)
            ct += g_part[((size_t)b * NCHUNK + c) * DDIM + d];
        out[i] = ct / (den + 1e-10f);
    } else if (i < BATCH * DDIM + L_MAX * BATCH) {
        int j = i - BATCH * DDIM;
        int b = j & (BATCH - 1);
        float den = 0.f;
#pragma unroll
        for (int c = 0; c < NCHUNK; c++) den += g_denp[b * NCHUNK + c];
        out[i] = g_hardU[j] / (den + 1e-10f);
    }
}

// ---------------------------------------------------------------------------
extern "C" void kernel_launch(void* const* d_in, const int* in_sizes, int n_in,
                              void* d_out, int out_size)
{
    (void)in_sizes; (void)n_in; (void)out_size;
    const float* ctx_val  = (const float*)d_in[0];
    const float* ctx_key  = (const float*)d_in[1];
    const float* ctx_mask = (const float*)d_in[2];
    const float* past     = (const float*)d_in[3];
    const float* ht       = (const float*)d_in[4];
    const float* Wc       = (const float*)d_in[5];
    const float* Wq       = (const float*)d_in[6];
    const float* Wap      = (const float*)d_in[7];
    const float* bap      = (const float*)d_in[8];
    const float* Wattn    = (const float*)d_in[9];
    const float* battn    = (const float*)d_in[10];
    float* out = (float*)d_out;

    prep_kernel<<<HQ_BLOCKS + M_BLOCKS, 256>>>(ht, Wq, Wap, Wc, bap);

    dim3 grid(NCHUNK, BATCH);
    score_kernel<<<grid, 256>>>(ctx_key, ctx_mask, past, Wattn, battn);
    val_kernel<<<grid, 256>>>(ctx_val);

    int total = BATCH * DDIM + L_MAX * BATCH;
    finish_kernel<<<(total + 255) / 256, 256>>>(out);
}

// round 9
// speedup vs baseline: 1.3476x; 1.3476x over previous
#include <cuda_runtime.h>

#define L_MAX   2048
#define BATCH   64
#define DDIM    256
#define CCH     512
#define NCHUNK  16
#define ROWS_PER_CHUNK (L_MAX / NCHUNK)   // 128
#define ROWS_PER_WARP  (ROWS_PER_CHUNK / 8) // 16

#define HQ_BLOCKS 2048
#define M_BLOCKS  96

// finish grid: 64 ct-blocks + 512 hard-blocks
#define CT_BLOCKS   BATCH
#define HARD_BLOCKS (L_MAX * BATCH / 256)   // 512

// ---- scratch (no allocations allowed) ----
__device__ float g_hq[BATCH * DDIM];
__device__ float g_M[3 * DDIM];
__device__ float g_hardU[L_MAX * BATCH];
__device__ float g_part[BATCH * NCHUNK * DDIM];
__device__ float g_denp[BATCH * NCHUNK];

__device__ __forceinline__ float ftanh(float x) {
    float e = __expf(2.0f * x);
    return 1.0f - __fdividef(2.0f, e + 1.0f);
}

// ---------------------------------------------------------------------------
// Kernel 1: prep (warp-per-output, fully coalesced). Unchanged (7.2 us).
// ---------------------------------------------------------------------------
__global__ __launch_bounds__(256) void prep_kernel(
    const float* __restrict__ ht, const float* __restrict__ Wq,
    const float* __restrict__ Wap, const float* __restrict__ Wc,
    const float* __restrict__ bap)
{
    int warp = threadIdx.x >> 5, lane = threadIdx.x & 31;

    if (blockIdx.x < HQ_BLOCKS) {
        int gw = blockIdx.x * 8 + warp;
        int b = gw >> 8;
        int d = gw & 255;
        const float* htr = ht + b * DDIM;
        const float* wqr = Wq + (size_t)d * DDIM;
        float a = 0.f;
#pragma unroll
        for (int i = 0; i < DDIM / 32; i++) {
            int e = lane + 32 * i;
            a += htr[e] * wqr[e];
        }
#pragma unroll
        for (int off = 16; off; off >>= 1)
            a += __shfl_xor_sync(0xffffffffu, a, off);
        if (lane == 0) g_hq[b * DDIM + d] = a + bap[d];
    } else {
        int gw = (blockIdx.x - HQ_BLOCKS) * 8 + warp;
        int dd = gw / 3;
        int k  = gw % 3;
        const float* wr = Wap + (size_t)dd * CCH;
        float m = 0.f;
#pragma unroll
        for (int i = 0; i < CCH / 32; i++) {
            int c = lane + 32 * i;
            m += wr[c] * Wc[c * 3 + k];
        }
#pragma unroll
        for (int off = 16; off; off >>= 1)
            m += __shfl_xor_sync(0xffffffffu, m, off);
        if (lane == 0) g_M[k * DDIM + dd] = m;
    }
}

// ---------------------------------------------------------------------------
// Kernel 2: main — R7 body (conditional val load, M + past in smem,
// 4 blocks/SM). Grid order swapped: blockIdx.x = b (fast) so a wave of CTAs
// streams one contiguous chunk-span of ctx_key/ctx_val.
// ---------------------------------------------------------------------------
__global__ __launch_bounds__(256, 4) void main_kernel(
    const float* __restrict__ ctx_val, const float* __restrict__ ctx_key,
    const float* __restrict__ ctx_mask, const float* __restrict__ past,
    const float* __restrict__ W_attn, const float* __restrict__ b_attn)
{
    __shared__ alignas(16) float s_M[3 * DDIM];     // fused conv weights
    __shared__ alignas(16) float s_acc[8 * DDIM];   // warp partials
    __shared__ alignas(16) float s_past[ROWS_PER_CHUNK + 4]; // halo, padded
    __shared__ float s_cnt[8];

    int b = blockIdx.x, chunk = blockIdx.y;
    int w = threadIdx.x >> 5, lane = threadIdx.x & 31;
    int d0 = lane * 4;        // [0,128)
    int d1 = 128 + lane * 4;  // [128,256)

    // stage block-shared constants
    if (threadIdx.x < 3 * DDIM / 4) {
        reinterpret_cast<float4*>(s_M)[threadIdx.x] =
            reinterpret_cast<const float4*>(g_M)[threadIdx.x];
    }
    {
        int i = threadIdx.x;
        if (i < ROWS_PER_CHUNK + 2) {
            int g = chunk * ROWS_PER_CHUNK + i - 1;  // l-1 .. l+128
            s_past[i] = (g >= 0 && g < L_MAX) ? past[b * L_MAX + g] : 0.f;
        }
    }
    __syncthreads();

    float4 hq0 = *reinterpret_cast<const float4*>(&g_hq[b * DDIM + d0]);
    float4 hq1 = *reinterpret_cast<const float4*>(&g_hq[b * DDIM + d1]);
    float4 Wa0 = *reinterpret_cast<const float4*>(&W_attn[d0]);
    float4 Wa1 = *reinterpret_cast<const float4*>(&W_attn[d1]);
    float ba = b_attn[0];

    float4 acc0 = make_float4(0.f, 0.f, 0.f, 0.f);
    float4 acc1 = make_float4(0.f, 0.f, 0.f, 0.f);
    float hsum = 0.f;

    int lbase = chunk * ROWS_PER_CHUNK + w * ROWS_PER_WARP;
    for (int r = 0; r < ROWS_PER_WARP; r++) {
        int l = lbase + r;
        int lr = w * ROWS_PER_WARP + r;            // local row in chunk
        size_t row = ((size_t)l * BATCH + b) * DDIM;
        float4 k0 = *reinterpret_cast<const float4*>(ctx_key + row + d0);
        float4 k1 = *reinterpret_cast<const float4*>(ctx_key + row + d1);

        float pm = s_past[lr];
        float p0 = s_past[lr + 1];
        float pp = s_past[lr + 2];

        float4 m00 = *reinterpret_cast<const float4*>(&s_M[d0]);
        float4 m01 = *reinterpret_cast<const float4*>(&s_M[d1]);
        float4 m10 = *reinterpret_cast<const float4*>(&s_M[DDIM + d0]);
        float4 m11 = *reinterpret_cast<const float4*>(&s_M[DDIM + d1]);
        float4 m20 = *reinterpret_cast<const float4*>(&s_M[2 * DDIM + d0]);
        float4 m21 = *reinterpret_cast<const float4*>(&s_M[2 * DDIM + d1]);

        float s;
        s  = Wa0.x * ftanh(k0.x + hq0.x + pm * m00.x + p0 * m10.x + pp * m20.x);
        s += Wa0.y * ftanh(k0.y + hq0.y + pm * m00.y + p0 * m10.y + pp * m20.y);
        s += Wa0.z * ftanh(k0.z + hq0.z + pm * m00.z + p0 * m10.z + pp * m20.z);
        s += Wa0.w * ftanh(k0.w + hq0.w + pm * m00.w + p0 * m10.w + pp * m20.w);
        s += Wa1.x * ftanh(k1.x + hq1.x + pm * m01.x + p0 * m11.x + pp * m21.x);
        s += Wa1.y * ftanh(k1.y + hq1.y + pm * m01.y + p0 * m11.y + pp * m21.y);
        s += Wa1.z * ftanh(k1.z + hq1.z + pm * m01.z + p0 * m11.z + pp * m21.z);
        s += Wa1.w * ftanh(k1.w + hq1.w + pm * m01.w + p0 * m11.w + pp * m21.w);

#pragma unroll
        for (int off = 16; off; off >>= 1)
            s += __shfl_xor_sync(0xffffffffu, s, off);

        float h = (s + ba >= 0.f) ? ctx_mask[l * BATCH + b] : 0.f;
        if (lane == 0) g_hardU[l * BATCH + b] = h;
        hsum += h;

        if (h != 0.f) {  // warp-uniform: skip ctx_val row entirely when h==0
            float4 v0 = *reinterpret_cast<const float4*>(ctx_val + row + d0);
            float4 v1 = *reinterpret_cast<const float4*>(ctx_val + row + d1);
            acc0.x += h * v0.x; acc0.y += h * v0.y;
            acc0.z += h * v0.z; acc0.w += h * v0.w;
            acc1.x += h * v1.x; acc1.y += h * v1.y;
            acc1.z += h * v1.z; acc1.w += h * v1.w;
        }
    }

    *reinterpret_cast<float4*>(&s_acc[w * DDIM + d0]) = acc0;
    *reinterpret_cast<float4*>(&s_acc[w * DDIM + d1]) = acc1;
    if (lane == 0) s_cnt[w] = hsum;
    __syncthreads();

    int d = threadIdx.x;
    float p = 0.f;
#pragma unroll
    for (int ww = 0; ww < 8; ww++) p += s_acc[ww * DDIM + d];
    g_part[((size_t)b * NCHUNK + chunk) * DDIM + d] = p;

    if (threadIdx.x == 0) {
        float c = 0.f;
#pragma unroll
        for (int ww = 0; ww < 8; ww++) c += s_cnt[ww];
        g_denp[b * NCHUNK + chunk] = c;
    }
}

// ---------------------------------------------------------------------------
// Kernel 3: finish v2 — block-level denominator reduction (smem), no
// per-thread 16x g_denp loops.
//   blocks [0,64):  ct part, one block per b.
//   blocks [64,..): hard part, 256 consecutive j per block (coalesced).
// ---------------------------------------------------------------------------
__global__ __launch_bounds__(256) void finish_kernel(float* __restrict__ out)
{
    if (blockIdx.x < CT_BLOCKS) {
        // ------- ct part: b = blockIdx.x, thread = d -------
        __shared__ float s_dp[NCHUNK];
        int b = blockIdx.x, d = threadIdx.x;
        if (threadIdx.x < NCHUNK)
            s_dp[threadIdx.x] = g_denp[b * NCHUNK + threadIdx.x];
        __syncthreads();
        float den = 0.f;
#pragma unroll
        for (int c = 0; c < NCHUNK; c++) den += s_dp[c];
        float ct = 0.f;
#pragma unroll
        for (int c = 0; c < NCHUNK; c++)
            ct += g_part[((size_t)b * NCHUNK + c) * DDIM + d];
        out[b * DDIM + d] = ct / (den + 1e-10f);
    } else {
        // ------- hard part: 256 consecutive j; b = j & 63 -------
        __shared__ float s_den[BATCH];
        if (threadIdx.x < BATCH) {
            int b = threadIdx.x;
            float den = 0.f;
#pragma unroll
            for (int c = 0; c < NCHUNK; c++) den += g_denp[b * NCHUNK + c];
            s_den[b] = den + 1e-10f;
        }
        __syncthreads();
        int j = (blockIdx.x - CT_BLOCKS) * 256 + threadIdx.x;
        int b = j & (BATCH - 1);
        out[BATCH * DDIM + j] = g_hardU[j] / s_den[b];
    }
}

// ---------------------------------------------------------------------------
extern "C" void kernel_launch(void* const* d_in, const int* in_sizes, int n_in,
                              void* d_out, int out_size)
{
    (void)in_sizes; (void)n_in; (void)out_size;
    const float* ctx_val  = (const float*)d_in[0];
    const float* ctx_key  = (const float*)d_in[1];
    const float* ctx_mask = (const float*)d_in[2];
    const float* past     = (const float*)d_in[3];
    const float* ht       = (const float*)d_in[4];
    const float* Wc       = (const float*)d_in[5];
    const float* Wq       = (const float*)d_in[6];
    const float* Wap      = (const float*)d_in[7];
    const float* bap      = (const float*)d_in[8];
    const float* Wattn    = (const float*)d_in[9];
    const float* battn    = (const float*)d_in[10];
    float* out = (float*)d_out;

    prep_kernel<<<HQ_BLOCKS + M_BLOCKS, 256>>>(ht, Wq, Wap, Wc, bap);

    dim3 grid(BATCH, NCHUNK);   // b fast-varying: wave streams one chunk span
    main_kernel<<<grid, 256>>>(ctx_val, ctx_key, ctx_mask, past, Wattn, battn);

    finish_kernel<<<CT_BLOCKS + HARD_BLOCKS, 256>>>(out);
}

// round 10
// speedup vs baseline: 1.4238x; 1.0566x over previous
#include <cuda_runtime.h>

#define L_MAX   2048
#define BATCH   64
#define DDIM    256
#define CCH     512
#define NCHUNK  16
#define ROWS_PER_CHUNK (L_MAX / NCHUNK)   // 128
#define ROWS_PER_WARP  (ROWS_PER_CHUNK / 8) // 16

#define HQ_BLOCKS 2048
#define M_BLOCKS  96

// finish grid: 64 ct-blocks + 512 hard-blocks
#define CT_BLOCKS   BATCH
#define HARD_BLOCKS (L_MAX * BATCH / 256)   // 512

// ---- scratch (no allocations allowed) ----
__device__ float g_hq[BATCH * DDIM];
__device__ float g_M[3 * DDIM];
__device__ float g_hardU[L_MAX * BATCH];
__device__ float g_part[BATCH * NCHUNK * DDIM];
__device__ float g_denp[BATCH * NCHUNK];

__device__ __forceinline__ float ftanh(float x) {
    float e = __expf(2.0f * x);
    return 1.0f - __fdividef(2.0f, e + 1.0f);
}

// ---------------------------------------------------------------------------
// Kernel 1: prep (warp-per-output, fully coalesced). Unchanged (7.2 us).
// ---------------------------------------------------------------------------
__global__ __launch_bounds__(256) void prep_kernel(
    const float* __restrict__ ht, const float* __restrict__ Wq,
    const float* __restrict__ Wap, const float* __restrict__ Wc,
    const float* __restrict__ bap)
{
    int warp = threadIdx.x >> 5, lane = threadIdx.x & 31;

    if (blockIdx.x < HQ_BLOCKS) {
        int gw = blockIdx.x * 8 + warp;
        int b = gw >> 8;
        int d = gw & 255;
        const float* htr = ht + b * DDIM;
        const float* wqr = Wq + (size_t)d * DDIM;
        float a = 0.f;
#pragma unroll
        for (int i = 0; i < DDIM / 32; i++) {
            int e = lane + 32 * i;
            a += htr[e] * wqr[e];
        }
#pragma unroll
        for (int off = 16; off; off >>= 1)
            a += __shfl_xor_sync(0xffffffffu, a, off);
        if (lane == 0) g_hq[b * DDIM + d] = a + bap[d];
    } else {
        int gw = (blockIdx.x - HQ_BLOCKS) * 8 + warp;
        int dd = gw / 3;
        int k  = gw % 3;
        const float* wr = Wap + (size_t)dd * CCH;
        float m = 0.f;
#pragma unroll
        for (int i = 0; i < CCH / 32; i++) {
            int c = lane + 32 * i;
            m += wr[c] * Wc[c * 3 + k];
        }
#pragma unroll
        for (int off = 16; off; off >>= 1)
            m += __shfl_xor_sync(0xffffffffu, m, off);
        if (lane == 0) g_M[k * DDIM + dd] = m;
    }
}

// ---------------------------------------------------------------------------
// Kernel 2: main — R7 body and R7 grid order (chunk fast-varying).
// Conditional val load, M + past halo in smem, 4 blocks/SM.
// ---------------------------------------------------------------------------
__global__ __launch_bounds__(256, 4) void main_kernel(
    const float* __restrict__ ctx_val, const float* __restrict__ ctx_key,
    const float* __restrict__ ctx_mask, const float* __restrict__ past,
    const float* __restrict__ W_attn, const float* __restrict__ b_attn)
{
    __shared__ alignas(16) float s_M[3 * DDIM];     // fused conv weights
    __shared__ alignas(16) float s_acc[8 * DDIM];   // warp partials
    __shared__ alignas(16) float s_past[ROWS_PER_CHUNK + 4]; // halo, padded
    __shared__ float s_cnt[8];

    int b = blockIdx.y, chunk = blockIdx.x;
    int w = threadIdx.x >> 5, lane = threadIdx.x & 31;
    int d0 = lane * 4;        // [0,128)
    int d1 = 128 + lane * 4;  // [128,256)

    // stage block-shared constants
    if (threadIdx.x < 3 * DDIM / 4) {
        reinterpret_cast<float4*>(s_M)[threadIdx.x] =
            reinterpret_cast<const float4*>(g_M)[threadIdx.x];
    }
    {
        int i = threadIdx.x;
        if (i < ROWS_PER_CHUNK + 2) {
            int g = chunk * ROWS_PER_CHUNK + i - 1;  // l-1 .. l+128
            s_past[i] = (g >= 0 && g < L_MAX) ? past[b * L_MAX + g] : 0.f;
        }
    }
    __syncthreads();

    float4 hq0 = *reinterpret_cast<const float4*>(&g_hq[b * DDIM + d0]);
    float4 hq1 = *reinterpret_cast<const float4*>(&g_hq[b * DDIM + d1]);
    float4 Wa0 = *reinterpret_cast<const float4*>(&W_attn[d0]);
    float4 Wa1 = *reinterpret_cast<const float4*>(&W_attn[d1]);
    float ba = b_attn[0];

    float4 acc0 = make_float4(0.f, 0.f, 0.f, 0.f);
    float4 acc1 = make_float4(0.f, 0.f, 0.f, 0.f);
    float hsum = 0.f;

    int lbase = chunk * ROWS_PER_CHUNK + w * ROWS_PER_WARP;
    for (int r = 0; r < ROWS_PER_WARP; r++) {
        int l = lbase + r;
        int lr = w * ROWS_PER_WARP + r;            // local row in chunk
        size_t row = ((size_t)l * BATCH + b) * DDIM;
        float4 k0 = *reinterpret_cast<const float4*>(ctx_key + row + d0);
        float4 k1 = *reinterpret_cast<const float4*>(ctx_key + row + d1);

        float pm = s_past[lr];
        float p0 = s_past[lr + 1];
        float pp = s_past[lr + 2];

        float4 m00 = *reinterpret_cast<const float4*>(&s_M[d0]);
        float4 m01 = *reinterpret_cast<const float4*>(&s_M[d1]);
        float4 m10 = *reinterpret_cast<const float4*>(&s_M[DDIM + d0]);
        float4 m11 = *reinterpret_cast<const float4*>(&s_M[DDIM + d1]);
        float4 m20 = *reinterpret_cast<const float4*>(&s_M[2 * DDIM + d0]);
        float4 m21 = *reinterpret_cast<const float4*>(&s_M[2 * DDIM + d1]);

        float s;
        s  = Wa0.x * ftanh(k0.x + hq0.x + pm * m00.x + p0 * m10.x + pp * m20.x);
        s += Wa0.y * ftanh(k0.y + hq0.y + pm * m00.y + p0 * m10.y + pp * m20.y);
        s += Wa0.z * ftanh(k0.z + hq0.z + pm * m00.z + p0 * m10.z + pp * m20.z);
        s += Wa0.w * ftanh(k0.w + hq0.w + pm * m00.w + p0 * m10.w + pp * m20.w);
        s += Wa1.x * ftanh(k1.x + hq1.x + pm * m01.x + p0 * m11.x + pp * m21.x);
        s += Wa1.y * ftanh(k1.y + hq1.y + pm * m01.y + p0 * m11.y + pp * m21.y);
        s += Wa1.z * ftanh(k1.z + hq1.z + pm * m01.z + p0 * m11.z + pp * m21.z);
        s += Wa1.w * ftanh(k1.w + hq1.w + pm * m01.w + p0 * m11.w + pp * m21.w);

#pragma unroll
        for (int off = 16; off; off >>= 1)
            s += __shfl_xor_sync(0xffffffffu, s, off);

        float h = (s + ba >= 0.f) ? ctx_mask[l * BATCH + b] : 0.f;
        if (lane == 0) g_hardU[l * BATCH + b] = h;
        hsum += h;

        if (h != 0.f) {  // warp-uniform: skip ctx_val row entirely when h==0
            float4 v0 = *reinterpret_cast<const float4*>(ctx_val + row + d0);
            float4 v1 = *reinterpret_cast<const float4*>(ctx_val + row + d1);
            acc0.x += h * v0.x; acc0.y += h * v0.y;
            acc0.z += h * v0.z; acc0.w += h * v0.w;
            acc1.x += h * v1.x; acc1.y += h * v1.y;
            acc1.z += h * v1.z; acc1.w += h * v1.w;
        }
    }

    *reinterpret_cast<float4*>(&s_acc[w * DDIM + d0]) = acc0;
    *reinterpret_cast<float4*>(&s_acc[w * DDIM + d1]) = acc1;
    if (lane == 0) s_cnt[w] = hsum;
    __syncthreads();

    int d = threadIdx.x;
    float p = 0.f;
#pragma unroll
    for (int ww = 0; ww < 8; ww++) p += s_acc[ww * DDIM + d];
    g_part[((size_t)b * NCHUNK + chunk) * DDIM + d] = p;

    if (threadIdx.x == 0) {
        float c = 0.f;
#pragma unroll
        for (int ww = 0; ww < 8; ww++) c += s_cnt[ww];
        g_denp[b * NCHUNK + chunk] = c;
    }
}

// ---------------------------------------------------------------------------
// Kernel 3: finish v2 — block-level denominator reduction (smem).
//   blocks [0,64):  ct part, one block per b.
//   blocks [64,..): hard part, 256 consecutive j per block (coalesced).
// ---------------------------------------------------------------------------
__global__ __launch_bounds__(256) void finish_kernel(float* __restrict__ out)
{
    if (blockIdx.x < CT_BLOCKS) {
        // ------- ct part: b = blockIdx.x, thread = d -------
        __shared__ float s_dp[NCHUNK];
        int b = blockIdx.x, d = threadIdx.x;
        if (threadIdx.x < NCHUNK)
            s_dp[threadIdx.x] = g_denp[b * NCHUNK + threadIdx.x];
        __syncthreads();
        float den = 0.f;
#pragma unroll
        for (int c = 0; c < NCHUNK; c++) den += s_dp[c];
        float ct = 0.f;
#pragma unroll
        for (int c = 0; c < NCHUNK; c++)
            ct += g_part[((size_t)b * NCHUNK + c) * DDIM + d];
        out[b * DDIM + d] = ct / (den + 1e-10f);
    } else {
        // ------- hard part: 256 consecutive j; b = j & 63 -------
        __shared__ float s_den[BATCH];
        if (threadIdx.x < BATCH) {
            int b = threadIdx.x;
            float den = 0.f;
#pragma unroll
            for (int c = 0; c < NCHUNK; c++) den += g_denp[b * NCHUNK + c];
            s_den[b] = den + 1e-10f;
        }
        __syncthreads();
        int j = (blockIdx.x - CT_BLOCKS) * 256 + threadIdx.x;
        int b = j & (BATCH - 1);
        out[BATCH * DDIM + j] = g_hardU[j] / s_den[b];
    }
}

// ---------------------------------------------------------------------------
extern "C" void kernel_launch(void* const* d_in, const int* in_sizes, int n_in,
                              void* d_out, int out_size)
{
    (void)in_sizes; (void)n_in; (void)out_size;
    const float* ctx_val  = (const float*)d_in[0];
    const float* ctx_key  = (const float*)d_in[1];
    const float* ctx_mask = (const float*)d_in[2];
    const float* past     = (const float*)d_in[3];
    const float* ht       = (const float*)d_in[4];
    const float* Wc       = (const float*)d_in[5];
    const float* Wq       = (const float*)d_in[6];
    const float* Wap      = (const float*)d_in[7];
    const float* bap      = (const float*)d_in[8];
    const float* Wattn    = (const float*)d_in[9];
    const float* battn    = (const float*)d_in[10];
    float* out = (float*)d_out;

    prep_kernel<<<HQ_BLOCKS + M_BLOCKS, 256>>>(ht, Wq, Wap, Wc, bap);

    dim3 grid(NCHUNK, BATCH);   // chunk fast-varying (R7 order — proven)
    main_kernel<<<grid, 256>>>(ctx_val, ctx_key, ctx_mask, past, Wattn, battn);

    finish_kernel<<<CT_BLOCKS + HARD_BLOCKS, 256>>>(out);
}

// round 11
// speedup vs baseline: 1.5543x; 1.0917x over previous
#include <cuda_runtime.h>

#define L_MAX   2048
#define BATCH   64
#define DDIM    256
#define CCH     512
#define NCHUNK  16
#define ROWS_PER_CHUNK (L_MAX / NCHUNK)   // 128
#define ROWS_PER_WARP  (ROWS_PER_CHUNK / 8) // 16

// prep: hq part = 256 d * 16 b-groups = 4096 warps = 512 blocks
#define HQ_BLOCKS 512
#define M_BLOCKS  96

// finish grid
#define CT_BLOCKS   BATCH
#define HARD_BLOCKS (L_MAX * BATCH / 256)   // 512

// ---- scratch (no allocations allowed) ----
__device__ float g_hq[BATCH * DDIM];
__device__ float g_M[3 * DDIM];
__device__ float g_hardU[L_MAX * BATCH];
__device__ float g_part[BATCH * NCHUNK * DDIM];
__device__ float g_denp[BATCH * NCHUNK];

__device__ __forceinline__ float ftanh(float x) {
    float e = __expf(2.0f * x);
    return 1.0f - __fdividef(2.0f, e + 1.0f);
}

// ---------------------------------------------------------------------------
// Kernel 1: prep v2.
//   hq: warp owns one d and 4 b's — Wq row loaded ONCE into regs; 4
//       interleaved reduce chains hide shfl latency. Wq traffic 16MB -> 4MB.
//   M:  unchanged warp-per-(k,d).
// ---------------------------------------------------------------------------
__global__ __launch_bounds__(256) void prep_kernel(
    const float* __restrict__ ht, const float* __restrict__ Wq,
    const float* __restrict__ Wap, const float* __restrict__ Wc,
    const float* __restrict__ bap)
{
    int warp = threadIdx.x >> 5, lane = threadIdx.x & 31;

    if (blockIdx.x < HQ_BLOCKS) {
        int gw = blockIdx.x * 8 + warp;   // [0, 4096)
        int d  = gw >> 4;
        int b0 = (gw & 15) * 4;
        const float* wqr = Wq + (size_t)d * DDIM;
        float wq[8];
#pragma unroll
        for (int i = 0; i < 8; i++) wq[i] = wqr[lane + 32 * i];

        float a0 = 0.f, a1 = 0.f, a2 = 0.f, a3 = 0.f;
#pragma unroll
        for (int i = 0; i < 8; i++) {
            int e = lane + 32 * i;
            a0 += ht[(b0 + 0) * DDIM + e] * wq[i];
            a1 += ht[(b0 + 1) * DDIM + e] * wq[i];
            a2 += ht[(b0 + 2) * DDIM + e] * wq[i];
            a3 += ht[(b0 + 3) * DDIM + e] * wq[i];
        }
#pragma unroll
        for (int off = 16; off; off >>= 1) {
            a0 += __shfl_xor_sync(0xffffffffu, a0, off);
            a1 += __shfl_xor_sync(0xffffffffu, a1, off);
            a2 += __shfl_xor_sync(0xffffffffu, a2, off);
            a3 += __shfl_xor_sync(0xffffffffu, a3, off);
        }
        if (lane < 4) {
            float a = (lane == 0) ? a0 : (lane == 1) ? a1 : (lane == 2) ? a2 : a3;
            g_hq[(b0 + lane) * DDIM + d] = a + bap[d];
        }
    } else {
        int gw = (blockIdx.x - HQ_BLOCKS) * 8 + warp;  // [0, 768)
        int dd = gw / 3;
        int k  = gw % 3;
        const float* wr = Wap + (size_t)dd * CCH;
        float m = 0.f;
#pragma unroll
        for (int i = 0; i < CCH / 32; i++) {
            int c = lane + 32 * i;
            m += wr[c] * Wc[c * 3 + k];
        }
#pragma unroll
        for (int off = 16; off; off >>= 1)
            m += __shfl_xor_sync(0xffffffffu, m, off);
        if (lane == 0) g_M[k * DDIM + dd] = m;
    }
}

// ---------------------------------------------------------------------------
// Kernel 2: main — batch-2 rows (2x key MLP, overlapped tanh/shfl chains),
// conditional val loads (traffic-minimal), mask+past+M staged in smem.
// ---------------------------------------------------------------------------
__global__ __launch_bounds__(256, 3) void main_kernel(
    const float* __restrict__ ctx_val, const float* __restrict__ ctx_key,
    const float* __restrict__ ctx_mask, const float* __restrict__ past,
    const float* __restrict__ W_attn, const float* __restrict__ b_attn)
{
    __shared__ alignas(16) float s_M[3 * DDIM];
    __shared__ alignas(16) float s_acc[8 * DDIM];
    __shared__ alignas(16) float s_past[ROWS_PER_CHUNK + 4];
    __shared__ alignas(16) float s_mask[ROWS_PER_CHUNK];
    __shared__ float s_cnt[8];

    int b = blockIdx.y, chunk = blockIdx.x;
    int w = threadIdx.x >> 5, lane = threadIdx.x & 31;
    int d0 = lane * 4;        // [0,128)
    int d1 = 128 + lane * 4;  // [128,256)

    // stage block-shared data
    if (threadIdx.x < 3 * DDIM / 4) {
        reinterpret_cast<float4*>(s_M)[threadIdx.x] =
            reinterpret_cast<const float4*>(g_M)[threadIdx.x];
    }
    {
        int i = threadIdx.x;
        if (i < ROWS_PER_CHUNK + 2) {
            int g = chunk * ROWS_PER_CHUNK + i - 1;
            s_past[i] = (g >= 0 && g < L_MAX) ? past[b * L_MAX + g] : 0.f;
        }
        if (i < ROWS_PER_CHUNK)
            s_mask[i] = ctx_mask[(chunk * ROWS_PER_CHUNK + i) * BATCH + b];
    }
    __syncthreads();

    float4 hq0 = *reinterpret_cast<const float4*>(&g_hq[b * DDIM + d0]);
    float4 hq1 = *reinterpret_cast<const float4*>(&g_hq[b * DDIM + d1]);
    float4 Wa0 = *reinterpret_cast<const float4*>(&W_attn[d0]);
    float4 Wa1 = *reinterpret_cast<const float4*>(&W_attn[d1]);
    float ba = b_attn[0];

    float4 acc0 = make_float4(0.f, 0.f, 0.f, 0.f);
    float4 acc1 = make_float4(0.f, 0.f, 0.f, 0.f);
    float hsum = 0.f;

    int lbase = chunk * ROWS_PER_CHUNK + w * ROWS_PER_WARP;
#pragma unroll 2
    for (int rb = 0; rb < ROWS_PER_WARP / 2; rb++) {
        int l0 = lbase + rb * 2;
        int lr0 = w * ROWS_PER_WARP + rb * 2;
        size_t row0 = ((size_t)l0 * BATCH + b) * DDIM;
        size_t row1 = row0 + (size_t)BATCH * DDIM;

        // 4 independent key LDG.128 up front
        float4 ka0 = *reinterpret_cast<const float4*>(ctx_key + row0 + d0);
        float4 kb0 = *reinterpret_cast<const float4*>(ctx_key + row0 + d1);
        float4 ka1 = *reinterpret_cast<const float4*>(ctx_key + row1 + d0);
        float4 kb1 = *reinterpret_cast<const float4*>(ctx_key + row1 + d1);

        float4 m00 = *reinterpret_cast<const float4*>(&s_M[d0]);
        float4 m01 = *reinterpret_cast<const float4*>(&s_M[d1]);
        float4 m10 = *reinterpret_cast<const float4*>(&s_M[DDIM + d0]);
        float4 m11 = *reinterpret_cast<const float4*>(&s_M[DDIM + d1]);
        float4 m20 = *reinterpret_cast<const float4*>(&s_M[2 * DDIM + d0]);
        float4 m21 = *reinterpret_cast<const float4*>(&s_M[2 * DDIM + d1]);

        float pm0 = s_past[lr0],     p00 = s_past[lr0 + 1], pp0 = s_past[lr0 + 2];
        float pm1 = s_past[lr0 + 1], p01 = s_past[lr0 + 2], pp1 = s_past[lr0 + 3];

        // two independent score chains, interleaved for MUFU overlap
        float s0, s1;
        s0  = Wa0.x * ftanh(ka0.x + hq0.x + pm0 * m00.x + p00 * m10.x + pp0 * m20.x);
        s1  = Wa0.x * ftanh(ka1.x + hq0.x + pm1 * m00.x + p01 * m10.x + pp1 * m20.x);
        s0 += Wa0.y * ftanh(ka0.y + hq0.y + pm0 * m00.y + p00 * m10.y + pp0 * m20.y);
        s1 += Wa0.y * ftanh(ka1.y + hq0.y + pm1 * m00.y + p01 * m10.y + pp1 * m20.y);
        s0 += Wa0.z * ftanh(ka0.z + hq0.z + pm0 * m00.z + p00 * m10.z + pp0 * m20.z);
        s1 += Wa0.z * ftanh(ka1.z + hq0.z + pm1 * m00.z + p01 * m10.z + pp1 * m20.z);
        s0 += Wa0.w * ftanh(ka0.w + hq0.w + pm0 * m00.w + p00 * m10.w + pp0 * m20.w);
        s1 += Wa0.w * ftanh(ka1.w + hq0.w + pm1 * m00.w + p01 * m10.w + pp1 * m20.w);
        s0 += Wa1.x * ftanh(kb0.x + hq1.x + pm0 * m01.x + p00 * m11.x + pp0 * m21.x);
        s1 += Wa1.x * ftanh(kb1.x + hq1.x + pm1 * m01.x + p01 * m11.x + pp1 * m21.x);
        s0 += Wa1.y * ftanh(kb0.y + hq1.y + pm0 * m01.y + p00 * m11.y + pp0 * m21.y);
        s1 += Wa1.y * ftanh(kb1.y + hq1.y + pm1 * m01.y + p01 * m11.y + pp1 * m21.y);
        s0 += Wa1.z * ftanh(kb0.z + hq1.z + pm0 * m01.z + p00 * m11.z + pp0 * m21.z);
        s1 += Wa1.z * ftanh(kb1.z + hq1.z + pm1 * m01.z + p01 * m11.z + pp1 * m21.z);
        s0 += Wa1.w * ftanh(kb0.w + hq1.w + pm0 * m01.w + p00 * m11.w + pp0 * m21.w);
        s1 += Wa1.w * ftanh(kb1.w + hq1.w + pm1 * m01.w + p01 * m11.w + pp1 * m21.w);

#pragma unroll
        for (int off = 16; off; off >>= 1) {
            s0 += __shfl_xor_sync(0xffffffffu, s0, off);
            s1 += __shfl_xor_sync(0xffffffffu, s1, off);
        }

        float h0 = (s0 + ba >= 0.f) ? s_mask[lr0] : 0.f;
        float h1 = (s1 + ba >= 0.f) ? s_mask[lr0 + 1] : 0.f;
        if (lane == 0) {
            g_hardU[l0 * BATCH + b] = h0;
            g_hardU[(l0 + 1) * BATCH + b] = h1;
        }
        hsum += h0 + h1;

        if (h0 != 0.f) {
            float4 v0 = *reinterpret_cast<const float4*>(ctx_val + row0 + d0);
            float4 v1 = *reinterpret_cast<const float4*>(ctx_val + row0 + d1);
            acc0.x += h0 * v0.x; acc0.y += h0 * v0.y;
            acc0.z += h0 * v0.z; acc0.w += h0 * v0.w;
            acc1.x += h0 * v1.x; acc1.y += h0 * v1.y;
            acc1.z += h0 * v1.z; acc1.w += h0 * v1.w;
        }
        if (h1 != 0.f) {
            float4 v0 = *reinterpret_cast<const float4*>(ctx_val + row1 + d0);
            float4 v1 = *reinterpret_cast<const float4*>(ctx_val + row1 + d1);
            acc0.x += h1 * v0.x; acc0.y += h1 * v0.y;
            acc0.z += h1 * v0.z; acc0.w += h1 * v0.w;
            acc1.x += h1 * v1.x; acc1.y += h1 * v1.y;
            acc1.z += h1 * v1.z; acc1.w += h1 * v1.w;
        }
    }

    *reinterpret_cast<float4*>(&s_acc[w * DDIM + d0]) = acc0;
    *reinterpret_cast<float4*>(&s_acc[w * DDIM + d1]) = acc1;
    if (lane == 0) s_cnt[w] = hsum;
    __syncthreads();

    int d = threadIdx.x;
    float p = 0.f;
#pragma unroll
    for (int ww = 0; ww < 8; ww++) p += s_acc[ww * DDIM + d];
    g_part[((size_t)b * NCHUNK + chunk) * DDIM + d] = p;

    if (threadIdx.x == 0) {
        float c = 0.f;
#pragma unroll
        for (int ww = 0; ww < 8; ww++) c += s_cnt[ww];
        g_denp[b * NCHUNK + chunk] = c;
    }
}

// ---------------------------------------------------------------------------
// Kernel 3: finish v2 (unchanged from R10).
// ---------------------------------------------------------------------------
__global__ __launch_bounds__(256) void finish_kernel(float* __restrict__ out)
{
    if (blockIdx.x < CT_BLOCKS) {
        __shared__ float s_dp[NCHUNK];
        int b = blockIdx.x, d = threadIdx.x;
        if (threadIdx.x < NCHUNK)
            s_dp[threadIdx.x] = g_denp[b * NCHUNK + threadIdx.x];
        __syncthreads();
        float den = 0.f;
#pragma unroll
        for (int c = 0; c < NCHUNK; c++) den += s_dp[c];
        float ct = 0.f;
#pragma unroll
        for (int c = 0; c < NCHUNK; c++)
            ct += g_part[((size_t)b * NCHUNK + c) * DDIM + d];
        out[b * DDIM + d] = ct / (den + 1e-10f);
    } else {
        __shared__ float s_den[BATCH];
        if (threadIdx.x < BATCH) {
            int b = threadIdx.x;
            float den = 0.f;
#pragma unroll
            for (int c = 0; c < NCHUNK; c++) den += g_denp[b * NCHUNK + c];
            s_den[b] = den + 1e-10f;
        }
        __syncthreads();
        int j = (blockIdx.x - CT_BLOCKS) * 256 + threadIdx.x;
        int b = j & (BATCH - 1);
        out[BATCH * DDIM + j] = g_hardU[j] / s_den[b];
    }
}

// ---------------------------------------------------------------------------
extern "C" void kernel_launch(void* const* d_in, const int* in_sizes, int n_in,
                              void* d_out, int out_size)
{
    (void)in_sizes; (void)n_in; (void)out_size;
    const float* ctx_val  = (const float*)d_in[0];
    const float* ctx_key  = (const float*)d_in[1];
    const float* ctx_mask = (const float*)d_in[2];
    const float* past     = (const float*)d_in[3];
    const float* ht       = (const float*)d_in[4];
    const float* Wc       = (const float*)d_in[5];
    const float* Wq       = (const float*)d_in[6];
    const float* Wap      = (const float*)d_in[7];
    const float* bap      = (const float*)d_in[8];
    const float* Wattn    = (const float*)d_in[9];
    const float* battn    = (const float*)d_in[10];
    float* out = (float*)d_out;

    prep_kernel<<<HQ_BLOCKS + M_BLOCKS, 256>>>(ht, Wq, Wap, Wc, bap);

    dim3 grid(NCHUNK, BATCH);   // chunk fast-varying (proven order)
    main_kernel<<<grid, 256>>>(ctx_val, ctx_key, ctx_mask, past, Wattn, battn);

    finish_kernel<<<CT_BLOCKS + HARD_BLOCKS, 256>>>(out);
}